// round 1
// baseline (speedup 1.0000x reference)
#include <cuda_runtime.h>
#include <math.h>

#define NN   512
#define CINC 64
#define HIDC 128
#define HWSZ 1024
#define HH   32
#define WW   32
#define HEADS 4
#define NE   16384
#define TOTE (NE + NN)

// ---------------- device scratch (no allocations allowed) ----------------
__device__ float g_bufA[NN * HIDC * HWSZ];   // xe, later xp(final)
__device__ float g_bufB[NN * HIDC * HWSZ];   // xp1
__device__ float g_xnode[NN * HIDC];
__device__ float g_hfeat[NN * HEADS * HIDC];
__device__ float g_as[NN * HEADS];
__device__ float g_ad[NN * HEADS];
__device__ float g_xg[NN * HIDC];
__device__ float g_gterm[NN * CINC];
__device__ int   g_cnt[NN];
__device__ int   g_row[NN + 1];
__device__ int   g_fill[NN];
__device__ int   g_csr[TOTE];
__device__ int   g_is64;

// ---------------- edge dtype detect + CSR build ----------------
__global__ void setup_kernel(const int* __restrict__ ei) {
    int t = threadIdx.x;
    if (t < NN) g_cnt[t] = 0;
    if (t == 0) {
        // If edge_index is int64 (little-endian), every high word of the
        // first 128 entries is 0 (values in [0,512)). If int32, these odd
        // int32 slots are random src values — P(all zero) ~ 0.
        int acc = 0;
        for (int i = 0; i < 128; i++) acc |= ei[2 * i + 1];
        g_is64 = (acc == 0) ? 1 : 0;
    }
}

__device__ __forceinline__ void read_edge(const int* __restrict__ ei, int i,
                                          int is64, int& s, int& d) {
    if (i < NE) {
        if (is64) { s = ei[2 * i]; d = ei[2 * (NE + i)]; }
        else      { s = ei[i];     d = ei[NE + i]; }
    } else {
        s = i - NE; d = i - NE;  // self loop
    }
}

__global__ void count_kernel(const int* __restrict__ ei) {
    int i = blockIdx.x * blockDim.x + threadIdx.x;
    if (i >= TOTE) return;
    int s, d;
    read_edge(ei, i, g_is64, s, d);
    atomicAdd(&g_cnt[d], 1);
}

__global__ void scan_kernel() {
    __shared__ int sc[NN];
    int t = threadIdx.x;
    int c = g_cnt[t];
    sc[t] = c;
    __syncthreads();
    for (int off = 1; off < NN; off <<= 1) {
        int v = (t >= off) ? sc[t - off] : 0;
        __syncthreads();
        sc[t] += v;
        __syncthreads();
    }
    g_row[t + 1] = sc[t];
    if (t == 0) g_row[0] = 0;
    g_fill[t] = sc[t] - c;   // exclusive prefix = running fill offset
}

__global__ void scatter_kernel(const int* __restrict__ ei) {
    int i = blockIdx.x * blockDim.x + threadIdx.x;
    if (i >= TOTE) return;
    int s, d;
    read_edge(ei, i, g_is64, s, d);
    int pos = atomicAdd(&g_fill[d], 1);
    g_csr[pos] = s;
}

// ---------------- fe: 1x1 conv + BN + ReLU + confidence ----------------
// grid (512, 8): n, 128-px tile. 256 thr = 32 px-grp(4px) x 8 o-grp(16o).
__global__ __launch_bounds__(256) void fe_kernel(
    const float* __restrict__ x, const float* __restrict__ fw,
    const float* __restrict__ fb, const float* __restrict__ fg,
    const float* __restrict__ fbe, const float* __restrict__ conf,
    float* __restrict__ xe) {
    __shared__ float xs[32 * 128];
    __shared__ float ws[32 * 128];
    int n = blockIdx.x, px0 = blockIdx.y * 128;
    int tid = threadIdx.x;
    int pg = tid & 31, og = tid >> 5;
    int px = pg * 4, ob = og * 16;
    float acc[16][4];
#pragma unroll
    for (int i = 0; i < 16; i++)
#pragma unroll
        for (int j = 0; j < 4; j++) acc[i][j] = 0.f;

    for (int kc = 0; kc < CINC; kc += 32) {
        __syncthreads();
        for (int idx = tid; idx < 32 * 128; idx += 256) {
            int k = idx >> 7, p = idx & 127;
            xs[idx] = x[(n * CINC + kc + k) * HWSZ + px0 + p];
            int o = idx & 127, k2 = idx >> 7;
            ws[idx] = fw[o * CINC + kc + k2];
        }
        __syncthreads();
#pragma unroll
        for (int k = 0; k < 32; k++) {
            float4 bx = *(const float4*)&xs[k * 128 + px];
#pragma unroll
            for (int jo = 0; jo < 4; jo++) {
                float4 av = *(const float4*)&ws[k * 128 + ob + jo * 4];
                float wv[4] = {av.x, av.y, av.z, av.w};
#pragma unroll
                for (int l = 0; l < 4; l++) {
                    acc[jo * 4 + l][0] += wv[l] * bx.x;
                    acc[jo * 4 + l][1] += wv[l] * bx.y;
                    acc[jo * 4 + l][2] += wv[l] * bx.z;
                    acc[jo * 4 + l][3] += wv[l] * bx.w;
                }
            }
        }
    }
    float4 cf = *(const float4*)&conf[n * HWSZ + px0 + px];
    const float inv = rsqrtf(1.0f + 1e-5f);
#pragma unroll
    for (int ol = 0; ol < 16; ol++) {
        int o = ob + ol;
        float sc = fg[o] * inv;
        float sh = fbe[o] + fb[o] * sc;
        float4 v;
        v.x = fmaxf(acc[ol][0] * sc + sh, 0.f) * cf.x;
        v.y = fmaxf(acc[ol][1] * sc + sh, 0.f) * cf.y;
        v.z = fmaxf(acc[ol][2] * sc + sh, 0.f) * cf.z;
        v.w = fmaxf(acc[ol][3] * sc + sh, 0.f) * cf.w;
        *(float4*)&xe[(n * HIDC + o) * HWSZ + px0 + px] = v;
    }
}

// ---------------- 3x3 conv + BN + ReLU ----------------
// grid (512, 4, 4): n, co-block(32), h-block(8 rows).
// 256 thr = 32 px-grp(1 row-strip of 8 cols) x 8 co-grp(4 co).
#define CI_CHUNK 16
#define IN_RS 35   // smem row stride (conflict-free: (3r+8s) mod 32 distinct)
__global__ __launch_bounds__(256, 2) void conv3x3_kernel(
    const float* __restrict__ in, const float* __restrict__ w,
    const float* __restrict__ bb, const float* __restrict__ gg,
    const float* __restrict__ be, float* __restrict__ out) {
    __shared__ float sIn[CI_CHUNK * 10 * IN_RS];
    __shared__ float sW[CI_CHUNK * 9 * 32];
    int n = blockIdx.x, cob = blockIdx.y, hb = blockIdx.z;
    int tid = threadIdx.x;
    int pxg = tid & 31, cog = tid >> 5;
    int row = pxg >> 2, cs = (pxg & 3) * 8;
    int h0 = hb * 8;

    float acc[4][8];
#pragma unroll
    for (int q = 0; q < 4; q++)
#pragma unroll
        for (int p = 0; p < 8; p++) acc[q][p] = 0.f;

    for (int cc = 0; cc < HIDC; cc += CI_CHUNK) {
        __syncthreads();
        // stage input tile (rows h0-1..h0+8, cols -1..32, zero-padded)
        for (int idx = tid; idx < CI_CHUNK * 10 * 34; idx += 256) {
            int ci = idx / 340;
            int rem = idx - ci * 340;
            int r = rem / 34;
            int c = rem - r * 34;
            int gh = h0 - 1 + r;
            int gw = c - 1;
            float v = 0.f;
            if ((unsigned)gh < 32u && (unsigned)gw < 32u)
                v = in[((n * HIDC + cc + ci) * HH + gh) * WW + gw];
            sIn[(ci * 10 + r) * IN_RS + c] = v;
        }
        // stage weights as [ci][tap][co32]
        for (int idx = tid; idx < CI_CHUNK * 9 * 32; idx += 256) {
            int col = idx & 31;
            int t2 = idx >> 5;
            int tap = t2 % 9;
            int ci = t2 / 9;
            sW[idx] = w[((cob * 32 + col) * HIDC + cc + ci) * 9 + tap];
        }
        __syncthreads();
#pragma unroll 1
        for (int ci = 0; ci < CI_CHUNK; ci++) {
            float a[3][10];
#pragma unroll
            for (int kh = 0; kh < 3; kh++)
#pragma unroll
                for (int j = 0; j < 10; j++)
                    a[kh][j] = sIn[(ci * 10 + row + kh) * IN_RS + cs + j];
#pragma unroll
            for (int tap = 0; tap < 9; tap++) {
                float4 wv = *(const float4*)&sW[(ci * 9 + tap) * 32 + cog * 4];
                int kh = tap / 3, kw = tap - kh * 3;
#pragma unroll
                for (int p = 0; p < 8; p++) {
                    float xv = a[kh][p + kw];
                    acc[0][p] += xv * wv.x;
                    acc[1][p] += xv * wv.y;
                    acc[2][p] += xv * wv.z;
                    acc[3][p] += xv * wv.w;
                }
            }
        }
    }
    const float inv = rsqrtf(1.0f + 1e-5f);
    int h = h0 + row;
#pragma unroll
    for (int q = 0; q < 4; q++) {
        int co = cob * 32 + cog * 4 + q;
        float sc = gg[co] * inv;
        float sh = be[co] + bb[co] * sc;
        float4 v0, v1;
        v0.x = fmaxf(acc[q][0] * sc + sh, 0.f);
        v0.y = fmaxf(acc[q][1] * sc + sh, 0.f);
        v0.z = fmaxf(acc[q][2] * sc + sh, 0.f);
        v0.w = fmaxf(acc[q][3] * sc + sh, 0.f);
        v1.x = fmaxf(acc[q][4] * sc + sh, 0.f);
        v1.y = fmaxf(acc[q][5] * sc + sh, 0.f);
        v1.z = fmaxf(acc[q][6] * sc + sh, 0.f);
        v1.w = fmaxf(acc[q][7] * sc + sh, 0.f);
        float* op = &out[((n * HIDC + co) * HH + h) * WW + cs];
        *(float4*)op = v0;
        *(float4*)(op + 4) = v1;
    }
}

// ---------------- global average pool ----------------
__global__ __launch_bounds__(128) void pool_kernel(const float* __restrict__ xp) {
    int bid = blockIdx.x;
    int n = bid >> 7, c = bid & 127;
    const float4* p = (const float4*)&xp[(n * HIDC + c) * HWSZ];
    float s = 0.f;
    for (int i = threadIdx.x; i < 256; i += 128) {
        float4 v = p[i];
        s += v.x + v.y + v.z + v.w;
    }
#pragma unroll
    for (int off = 16; off > 0; off >>= 1)
        s += __shfl_xor_sync(0xffffffffu, s, off);
    __shared__ float wsum[4];
    if ((threadIdx.x & 31) == 0) wsum[threadIdx.x >> 5] = s;
    __syncthreads();
    if (threadIdx.x == 0)
        g_xnode[n * HIDC + c] = (wsum[0] + wsum[1] + wsum[2] + wsum[3]) * (1.f / 1024.f);
}

// ---------------- GAT: h = x@lin, a_s, a_d ----------------
__global__ __launch_bounds__(128) void gat_h_kernel(
    const float* __restrict__ xin, const float* __restrict__ lin,
    const float* __restrict__ asw, const float* __restrict__ adw) {
    int n = blockIdx.x, t = threadIdx.x;
    __shared__ float xr[HIDC];
    __shared__ float red[HIDC];
    xr[t] = xin[n * HIDC + t];
    __syncthreads();
    float hv[HEADS];
#pragma unroll
    for (int j = 0; j < HEADS; j++) {
        int col = j * HIDC + t;
        float s = 0.f;
        for (int k = 0; k < HIDC; k++) s += xr[k] * lin[k * (HEADS * HIDC) + col];
        hv[j] = s;
        g_hfeat[n * (HEADS * HIDC) + col] = s;
    }
#pragma unroll
    for (int j = 0; j < HEADS; j++) {
        red[t] = hv[j] * asw[j * HIDC + t];
        __syncthreads();
        for (int off = 64; off > 0; off >>= 1) {
            if (t < off) red[t] += red[t + off];
            __syncthreads();
        }
        if (t == 0) g_as[n * HEADS + j] = red[0];
        __syncthreads();
        red[t] = hv[j] * adw[j * HIDC + t];
        __syncthreads();
        for (int off = 64; off > 0; off >>= 1) {
            if (t < off) red[t] += red[t + off];
            __syncthreads();
        }
        if (t == 0) g_ad[n * HEADS + j] = red[0];
        __syncthreads();
    }
}

// ---------------- GAT: per-dst softmax + aggregate + head mean + relu ----
__global__ __launch_bounds__(128) void gat_aggr_kernel(
    const float* __restrict__ bias, float* __restrict__ xout) {
    int n = blockIdx.x, t = threadIdx.x;
    float adn[HEADS];
#pragma unroll
    for (int j = 0; j < HEADS; j++) adn[j] = g_ad[n * HEADS + j];
    int rs = g_row[n], re = g_row[n + 1];
    float mx[HEADS] = {-1e30f, -1e30f, -1e30f, -1e30f};
    for (int ei = rs; ei < re; ei++) {
        int s = g_csr[ei];
#pragma unroll
        for (int j = 0; j < HEADS; j++) {
            float e = g_as[s * HEADS + j] + adn[j];
            e = (e > 0.f) ? e : 0.2f * e;
            mx[j] = fmaxf(mx[j], e);
        }
    }
    float den[HEADS] = {0.f, 0.f, 0.f, 0.f};
    float acc[HEADS] = {0.f, 0.f, 0.f, 0.f};
    for (int ei = rs; ei < re; ei++) {
        int s = g_csr[ei];
#pragma unroll
        for (int j = 0; j < HEADS; j++) {
            float e = g_as[s * HEADS + j] + adn[j];
            e = (e > 0.f) ? e : 0.2f * e;
            float ex = __expf(e - mx[j]);
            den[j] += ex;
            acc[j] += ex * g_hfeat[s * (HEADS * HIDC) + j * HIDC + t];
        }
    }
    float o = 0.f;
#pragma unroll
    for (int j = 0; j < HEADS; j++) o += acc[j] / (den[j] + 1e-16f);
    o = o * 0.25f + bias[t];
    xout[n * HIDC + t] = fmaxf(o, 0.f);
}

// ---------------- gterm[n,c] = op_b[c] + sum_o xg[n,o]*op_w[c,o] ----------
__global__ __launch_bounds__(64) void gterm_kernel(
    const float* __restrict__ opw, const float* __restrict__ opb) {
    int n = blockIdx.x, t = threadIdx.x;
    __shared__ float xg[HIDC];
    xg[t] = g_xg[n * HIDC + t];
    xg[t + 64] = g_xg[n * HIDC + t + 64];
    __syncthreads();
    float s = opb[t];
    for (int o = 0; o < HIDC; o++) s += xg[o] * opw[t * HIDC + o];
    g_gterm[n * CINC + t] = s;
}

// ---------------- op: out = gterm + xp @ op_w^T ----------------
// grid (512, 8): n, 128-px tile. 256 thr = 32 px-grp(4px) x 8 co-grp(8co).
__global__ __launch_bounds__(256) void op_kernel(
    const float* __restrict__ xp, const float* __restrict__ opw,
    float* __restrict__ out) {
    __shared__ float xs[32 * 128];
    __shared__ float ws[32 * 64];
    int n = blockIdx.x, px0 = blockIdx.y * 128;
    int tid = threadIdx.x;
    int pg = tid & 31, cog = tid >> 5;
    int px = pg * 4, cb = cog * 8;
    float acc[8][4];
#pragma unroll
    for (int i = 0; i < 8; i++)
#pragma unroll
        for (int j = 0; j < 4; j++) acc[i][j] = 0.f;

    for (int kc = 0; kc < HIDC; kc += 32) {
        __syncthreads();
        for (int idx = tid; idx < 32 * 128; idx += 256) {
            int k = idx >> 7, p = idx & 127;
            xs[idx] = xp[(n * HIDC + kc + k) * HWSZ + px0 + p];
        }
        for (int idx = tid; idx < 32 * 64; idx += 256) {
            int k = idx >> 6, c = idx & 63;
            ws[idx] = opw[c * HIDC + kc + k];
        }
        __syncthreads();
#pragma unroll
        for (int k = 0; k < 32; k++) {
            float4 bx = *(const float4*)&xs[k * 128 + px];
            float4 a0 = *(const float4*)&ws[k * 64 + cb];
            float4 a1 = *(const float4*)&ws[k * 64 + cb + 4];
            float wv[8] = {a0.x, a0.y, a0.z, a0.w, a1.x, a1.y, a1.z, a1.w};
#pragma unroll
            for (int l = 0; l < 8; l++) {
                acc[l][0] += wv[l] * bx.x;
                acc[l][1] += wv[l] * bx.y;
                acc[l][2] += wv[l] * bx.z;
                acc[l][3] += wv[l] * bx.w;
            }
        }
    }
#pragma unroll
    for (int l = 0; l < 8; l++) {
        int c = cb + l;
        float gt = g_gterm[n * CINC + c];
        float4 v;
        v.x = acc[l][0] + gt;
        v.y = acc[l][1] + gt;
        v.z = acc[l][2] + gt;
        v.w = acc[l][3] + gt;
        *(float4*)&out[(n * CINC + c) * HWSZ + px0 + px] = v;
    }
}

// ---------------- launch ----------------
extern "C" void kernel_launch(void* const* d_in, const int* in_sizes, int n_in,
                              void* d_out, int out_size) {
    const float* x    = (const float*)d_in[0];
    const int*   ei   = (const int*)d_in[1];
    const float* conf = (const float*)d_in[2];
    const float* fe_w = (const float*)d_in[3];
    const float* fe_b = (const float*)d_in[4];
    const float* fe_g = (const float*)d_in[5];
    const float* fe_be= (const float*)d_in[6];
    const float* sp_w1= (const float*)d_in[7];
    const float* sp_b1= (const float*)d_in[8];
    const float* sp_g1= (const float*)d_in[9];
    const float* sp_e1= (const float*)d_in[10];
    const float* sp_w2= (const float*)d_in[11];
    const float* sp_b2= (const float*)d_in[12];
    const float* sp_g2= (const float*)d_in[13];
    const float* sp_e2= (const float*)d_in[14];
    const float* g1_lin=(const float*)d_in[15];
    const float* g1_as= (const float*)d_in[16];
    const float* g1_ad= (const float*)d_in[17];
    const float* g1_b = (const float*)d_in[18];
    const float* g2_lin=(const float*)d_in[19];
    const float* g2_as= (const float*)d_in[20];
    const float* g2_ad= (const float*)d_in[21];
    const float* g2_b = (const float*)d_in[22];
    const float* op_w = (const float*)d_in[23];
    const float* op_b = (const float*)d_in[24];
    float* out = (float*)d_out;

    void *pA, *pB, *pXn, *pXg;
    cudaGetSymbolAddress(&pA, g_bufA);
    cudaGetSymbolAddress(&pB, g_bufB);
    cudaGetSymbolAddress(&pXn, g_xnode);
    cudaGetSymbolAddress(&pXg, g_xg);
    float* bufA = (float*)pA;
    float* bufB = (float*)pB;
    float* xnode = (float*)pXn;
    float* xg = (float*)pXg;

    // CSR build (per call; deterministic work)
    setup_kernel<<<1, 512>>>(ei);
    count_kernel<<<(TOTE + 255) / 256, 256>>>(ei);
    scan_kernel<<<1, 512>>>();
    scatter_kernel<<<(TOTE + 255) / 256, 256>>>(ei);

    // feature encoder -> bufA (xe)
    fe_kernel<<<dim3(NN, 8), 256>>>(x, fe_w, fe_b, fe_g, fe_be, conf, bufA);
    // spatial processor
    conv3x3_kernel<<<dim3(NN, 4, 4), 256>>>(bufA, sp_w1, sp_b1, sp_g1, sp_e1, bufB);
    conv3x3_kernel<<<dim3(NN, 4, 4), 256>>>(bufB, sp_w2, sp_b2, sp_g2, sp_e2, bufA);
    // pool (bufA = xp)
    pool_kernel<<<NN * HIDC, 128>>>(bufA);
    // GAT layer 1
    gat_h_kernel<<<NN, 128>>>(xnode, g1_lin, g1_as, g1_ad);
    gat_aggr_kernel<<<NN, 128>>>(g1_b, xg);
    // GAT layer 2
    gat_h_kernel<<<NN, 128>>>(xg, g2_lin, g2_as, g2_ad);
    gat_aggr_kernel<<<NN, 128>>>(g2_b, xg);
    // output projection
    gterm_kernel<<<NN, 64>>>(op_w, op_b);
    op_kernel<<<dim3(NN, 8), 256>>>(bufA, op_w, out);

    (void)in_sizes; (void)n_in; (void)out_size;
}